// round 12
// baseline (speedup 1.0000x reference)
#include <cuda_runtime.h>
#include <cstdint>

#define K_DIM   8192
#define B_DIM   256
#define OUT_DIM 8192
#define BM      128
#define BN      128
#define KC      64                     // int8 elems per stage (64B rows)
#define NT      (K_DIM / KC)           // 128 stages
#define RSTRIDE 80                     // bytes per smem row (64B + 16B pad)
#define SPLIT_BYTES (128 * RSTRIDE)    // 10240 per tile
#define STAGE_BYTES (4 * SPLIT_BYTES)  // Aq1|Aq2|Bq1|Bq2 = 40960
#define NSTAGE  5
#define DSMEM_BYTES (NSTAGE * STAGE_BYTES)  // 204800

// ---------------- scratch ----------------
__device__ int8_t g_xq1[(size_t)B_DIM * K_DIM];
__device__ int8_t g_xq2[(size_t)B_DIM * K_DIM];
__device__ int8_t g_wq1[(size_t)OUT_DIM * K_DIM];
__device__ int8_t g_wq2[(size_t)OUT_DIM * K_DIM];
__device__ float  g_sx[B_DIM];
__device__ float  g_sw[OUT_DIM];

// ---------------- helpers ----------------
__device__ __forceinline__ uint32_t smem_u32(const void* p) {
    uint32_t a;
    asm("{ .reg .u64 t; cvta.to.shared.u64 t, %1; cvt.u32.u64 %0, t; }" : "=r"(a) : "l"(p));
    return a;
}
__device__ __forceinline__ int q8(float v) {
    int q = __float2int_rn(v);
    return max(-127, min(127, q));
}
__device__ __forceinline__ uint32_t pack4(int a, int b, int c, int d) {
    return (uint32_t)(a & 0xFF) | ((uint32_t)(b & 0xFF) << 8) |
           ((uint32_t)(c & 0xFF) << 16) | ((uint32_t)(d & 0xFF) << 24);
}

#define LDSM4(r0, r1, r2, r3, addr) \
    asm volatile("ldmatrix.sync.aligned.m8n8.x4.shared.b16 {%0,%1,%2,%3}, [%4];" \
                 : "=r"(r0), "=r"(r1), "=r"(r2), "=r"(r3) : "r"(addr))

#define MMAS8(c, a, b) \
    asm volatile("mma.sync.aligned.m16n8k32.row.col.s32.s8.s8.s32 " \
                 "{%0,%1,%2,%3}, {%4,%5,%6,%7}, {%8,%9}, {%0,%1,%2,%3};" \
                 : "+r"((c)[0]), "+r"((c)[1]), "+r"((c)[2]), "+r"((c)[3]) \
                 : "r"((a)[0]), "r"((a)[1]), "r"((a)[2]), "r"((a)[3]), \
                   "r"((b)[0]), "r"((b)[1]))

#define CP_ASYNC16(dst, src) \
    asm volatile("cp.async.cg.shared.global [%0], [%1], 16;" :: "r"(dst), "l"(src) : "memory")
#define CP_COMMIT() asm volatile("cp.async.commit_group;" ::: "memory")
#define CP_WAIT3()  asm volatile("cp.async.wait_group 3;" ::: "memory")

// ---------------- kernel 1: quantize x (2 limbs, per-row scale) ----------------
__global__ __launch_bounds__(256)
void quant_x_kernel(const float* __restrict__ x) {
    __shared__ float red[256];
    const int row = blockIdx.x;
    const int t = threadIdx.x;
    const float* xr = x + (size_t)row * K_DIM;

    float4 v[8];
    float mx = 0.f;
    #pragma unroll
    for (int it = 0; it < 8; ++it) {
        v[it] = *reinterpret_cast<const float4*>(xr + t * 4 + it * 1024);
        mx = fmaxf(mx, fmaxf(fmaxf(fabsf(v[it].x), fabsf(v[it].y)),
                             fmaxf(fabsf(v[it].z), fabsf(v[it].w))));
    }
    red[t] = mx; __syncthreads();
    #pragma unroll
    for (int s = 128; s > 0; s >>= 1) {
        if (t < s) red[t] = fmaxf(red[t], red[t + s]);
        __syncthreads();
    }
    const float m = fmaxf(red[0], 1e-20f);
    const float sx = m / 127.f;
    const float inv = 127.f / m;
    const float inv2 = 254.f / sx;
    if (t == 0) g_sx[row] = sx;

    uint32_t* o1 = reinterpret_cast<uint32_t*>(g_xq1 + (size_t)row * K_DIM);
    uint32_t* o2 = reinterpret_cast<uint32_t*>(g_xq2 + (size_t)row * K_DIM);
    #pragma unroll
    for (int it = 0; it < 8; ++it) {
        const float4 a = v[it];
        int q0 = q8(a.x * inv), q1 = q8(a.y * inv), q2 = q8(a.z * inv), q3 = q8(a.w * inv);
        int p0 = q8((a.x - q0 * sx) * inv2), p1 = q8((a.y - q1 * sx) * inv2);
        int p2 = q8((a.z - q2 * sx) * inv2), p3 = q8((a.w - q3 * sx) * inv2);
        o1[t + it * 256] = pack4(q0, q1, q2, q3);
        o2[t + it * 256] = pack4(p0, p1, p2, p3);
    }
}

// ---------------- kernel 2: quantize W (2 limbs) + exact IBP bounds ----------------
__global__ __launch_bounds__(256)
void quant_w_kernel(const float* __restrict__ W,
                    const float* __restrict__ low,
                    const float* __restrict__ high,
                    const float* __restrict__ bias,
                    float* __restrict__ low_out,
                    float* __restrict__ high_out) {
    __shared__ float red[256];
    const int row = blockIdx.x;
    const int t = threadIdx.x;
    const float* wr = W + (size_t)row * K_DIM;

    float4 v[8];
    float mx = 0.f;
    #pragma unroll
    for (int it = 0; it < 8; ++it) {
        v[it] = *reinterpret_cast<const float4*>(wr + t * 4 + it * 1024);
        mx = fmaxf(mx, fmaxf(fmaxf(fabsf(v[it].x), fabsf(v[it].y)),
                             fmaxf(fabsf(v[it].z), fabsf(v[it].w))));
    }
    red[t] = mx; __syncthreads();
    #pragma unroll
    for (int s = 128; s > 0; s >>= 1) {
        if (t < s) red[t] = fmaxf(red[t], red[t + s]);
        __syncthreads();
    }
    const float m = fmaxf(red[0], 1e-20f);
    const float sw = m / 127.f;
    const float inv = 127.f / m;
    const float inv2 = 254.f / sw;
    if (t == 0) g_sw[row] = sw;
    __syncthreads();   // red[] reused below

    uint32_t* o1 = reinterpret_cast<uint32_t*>(g_wq1 + (size_t)row * K_DIM);
    uint32_t* o2 = reinterpret_cast<uint32_t*>(g_wq2 + (size_t)row * K_DIM);
    float accLo = 0.f, accHi = 0.f;
    #pragma unroll
    for (int it = 0; it < 8; ++it) {
        const float4 a = v[it];
        int q0 = q8(a.x * inv), q1 = q8(a.y * inv), q2 = q8(a.z * inv), q3 = q8(a.w * inv);
        int p0 = q8((a.x - q0 * sw) * inv2), p1 = q8((a.y - q1 * sw) * inv2);
        int p2 = q8((a.z - q2 * sw) * inv2), p3 = q8((a.w - q3 * sw) * inv2);
        o1[t + it * 256] = pack4(q0, q1, q2, q3);
        o2[t + it * 256] = pack4(p0, p1, p2, p3);
        // exact fp32 IBP bounds from the ORIGINAL W values
        const int c = t * 4 + it * 1024;
        const float4 la = *reinterpret_cast<const float4*>(low + c);
        const float4 ha = *reinterpret_cast<const float4*>(high + c);
        float p, q;
        p = a.x * la.x; q = a.x * ha.x; accLo += fminf(p, q); accHi += fmaxf(p, q);
        p = a.y * la.y; q = a.y * ha.y; accLo += fminf(p, q); accHi += fmaxf(p, q);
        p = a.z * la.z; q = a.z * ha.z; accLo += fminf(p, q); accHi += fmaxf(p, q);
        p = a.w * la.w; q = a.w * ha.w; accLo += fminf(p, q); accHi += fmaxf(p, q);
    }
    red[t] = accLo; __syncthreads();
    #pragma unroll
    for (int s = 128; s > 0; s >>= 1) {
        if (t < s) red[t] += red[t + s];
        __syncthreads();
    }
    const float loSum = red[0];
    __syncthreads();
    red[t] = accHi; __syncthreads();
    #pragma unroll
    for (int s = 128; s > 0; s >>= 1) {
        if (t < s) red[t] += red[t + s];
        __syncthreads();
    }
    if (t == 0) {
        const float bb = bias[row];
        low_out[row]  = loSum + bb;
        high_out[row] = red[0] + bb;
    }
}

// ---------------- kernel 3: int8 dual-limb GEMM ----------------
__global__ __launch_bounds__(256, 1)
void abstract_linear_s8_kernel(const float* __restrict__ bias,
                               float* __restrict__ y)
{
    extern __shared__ __align__(128) char dsm[];
    const uint32_t sbase = smem_u32(dsm);

    const int tid  = threadIdx.x;
    const int lane = tid & 31;
    const int wid  = tid >> 5;
    const int mBase = blockIdx.x * BM;   // m fast: W shared in L2 across m-CTAs
    const int nBase = blockIdx.y * BN;

    const int wm = wid >> 2;   // 0..1
    const int wn = wid & 3;    // 0..3

    // cp.async loader: 4 groups of 64 threads; thread -> 2 rows of one tile
    const int grp = tid >> 6;             // 0:Aq1 1:Aq2 2:Bq1 3:Bq2
    const int r0  = (tid & 63) * 2;
    const int8_t* gsrc;
    if      (grp == 0) gsrc = g_xq1 + (size_t)(mBase + r0) * K_DIM;
    else if (grp == 1) gsrc = g_xq2 + (size_t)(mBase + r0) * K_DIM;
    else if (grp == 2) gsrc = g_wq1 + (size_t)(nBase + r0) * K_DIM;
    else               gsrc = g_wq2 + (size_t)(nBase + r0) * K_DIM;
    const uint32_t dstBase = (uint32_t)grp * SPLIT_BYTES + (uint32_t)r0 * RSTRIDE;

    const uint32_t aOff = (uint32_t)(wm * 64 + (lane & 15)) * RSTRIDE + (lane >> 4) * 16;
    const uint32_t bOff = (uint32_t)(wn * 32 + (lane & 7) + ((lane >> 4) & 1) * 8) * RSTRIDE
                        + ((lane >> 3) & 1) * 16;

    int Dm[4][4][4], Dc[4][4][4];
    #pragma unroll
    for (int i = 0; i < 4; ++i)
        #pragma unroll
        for (int j = 0; j < 4; ++j)
            #pragma unroll
            for (int r = 0; r < 4; ++r) { Dm[i][j][r] = 0; Dc[i][j][r] = 0; }

    auto cpX = [&](int stage, int kt) {
        uint32_t dst = sbase + stage * STAGE_BYTES + dstBase;
        const int8_t* src = gsrc + (size_t)kt * KC;
        CP_ASYNC16(dst,      src);      CP_ASYNC16(dst + 16, src + 16);
        CP_ASYNC16(dst + 32, src + 32); CP_ASYNC16(dst + 48, src + 48);
        dst += RSTRIDE; src += K_DIM;
        CP_ASYNC16(dst,      src);      CP_ASYNC16(dst + 16, src + 16);
        CP_ASYNC16(dst + 32, src + 32); CP_ASYNC16(dst + 48, src + 48);
        CP_COMMIT();
    };

    auto doMMA = [&](int stage) {
        const uint32_t A1 = sbase + stage * STAGE_BYTES;
        const uint32_t A2 = A1 + SPLIT_BYTES;
        const uint32_t B1 = A1 + 2 * SPLIT_BYTES;
        const uint32_t B2 = A1 + 3 * SPLIT_BYTES;
        #pragma unroll
        for (int ks = 0; ks < 2; ++ks) {       // two k32 steps (32B each)
            uint32_t a1[4][4], a2[4][4], b1[4][2], b2[4][2];
            #pragma unroll
            for (int mf = 0; mf < 4; ++mf) {
                LDSM4(a1[mf][0], a1[mf][1], a1[mf][2], a1[mf][3],
                      A1 + aOff + mf * (16 * RSTRIDE) + ks * 32);
                LDSM4(a2[mf][0], a2[mf][1], a2[mf][2], a2[mf][3],
                      A2 + aOff + mf * (16 * RSTRIDE) + ks * 32);
            }
            #pragma unroll
            for (int p = 0; p < 2; ++p) {
                uint32_t q0, q1, q2, q3;
                LDSM4(q0, q1, q2, q3, B1 + bOff + p * (16 * RSTRIDE) + ks * 32);
                b1[2 * p][0] = q0; b1[2 * p][1] = q1;
                b1[2 * p + 1][0] = q2; b1[2 * p + 1][1] = q3;
                LDSM4(q0, q1, q2, q3, B2 + bOff + p * (16 * RSTRIDE) + ks * 32);
                b2[2 * p][0] = q0; b2[2 * p][1] = q1;
                b2[2 * p + 1][0] = q2; b2[2 * p + 1][1] = q3;
            }
            // term-major: 16 independent MMAs between accumulator reuses
            #pragma unroll
            for (int mf = 0; mf < 4; ++mf)
                #pragma unroll
                for (int nf = 0; nf < 4; ++nf) MMAS8(Dm[mf][nf], a1[mf], b1[nf]);
            #pragma unroll
            for (int mf = 0; mf < 4; ++mf)
                #pragma unroll
                for (int nf = 0; nf < 4; ++nf) MMAS8(Dc[mf][nf], a1[mf], b2[nf]);
            #pragma unroll
            for (int mf = 0; mf < 4; ++mf)
                #pragma unroll
                for (int nf = 0; nf < 4; ++nf) MMAS8(Dc[mf][nf], a2[mf], b1[nf]);
        }
    };

    // prologue: stages 0..3 in flight
    cpX(0, 0); cpX(1, 1); cpX(2, 2); cpX(3, 3);
    CP_WAIT3();
    __syncthreads();

    #pragma unroll 1
    for (int kt = 0; kt < NT; ++kt) {
        const int stage = kt % NSTAGE;
        if (kt + 4 < NT) cpX((kt + 4) % NSTAGE, kt + 4);
        else             CP_COMMIT();          // keep group counting aligned
        doMMA(stage);
        CP_WAIT3();
        __syncthreads();
    }

    // epilogue: y = sx*sw*(Dm + Dc/254) + bias
    #pragma unroll
    for (int mf = 0; mf < 4; ++mf) {
        const int rr = mBase + wm * 64 + mf * 16 + (lane >> 2);
        const float sx0 = g_sx[rr], sx1 = g_sx[rr + 8];
        #pragma unroll
        for (int nf = 0; nf < 4; ++nf) {
            const int c = nBase + wn * 32 + nf * 8 + (lane & 3) * 2;
            const float sw0 = g_sw[c], sw1 = g_sw[c + 1];
            const float2 bv = *reinterpret_cast<const float2*>(bias + c);
            const float k = 1.f / 254.f;
            float d00 = (float)Dm[mf][nf][0] + (float)Dc[mf][nf][0] * k;
            float d01 = (float)Dm[mf][nf][1] + (float)Dc[mf][nf][1] * k;
            float d10 = (float)Dm[mf][nf][2] + (float)Dc[mf][nf][2] * k;
            float d11 = (float)Dm[mf][nf][3] + (float)Dc[mf][nf][3] * k;
            float2 o0 = make_float2(sx0 * sw0 * d00 + bv.x, sx0 * sw1 * d01 + bv.y);
            float2 o1 = make_float2(sx1 * sw0 * d10 + bv.x, sx1 * sw1 * d11 + bv.y);
            *reinterpret_cast<float2*>(y + (size_t)rr * OUT_DIM + c) = o0;
            *reinterpret_cast<float2*>(y + (size_t)(rr + 8) * OUT_DIM + c) = o1;
        }
    }
}

extern "C" void kernel_launch(void* const* d_in, const int* in_sizes, int n_in,
                              void* d_out, int out_size) {
    const float* x    = (const float*)d_in[0];
    const float* low  = (const float*)d_in[1];
    const float* high = (const float*)d_in[2];
    const float* W    = (const float*)d_in[3];
    const float* bias = (const float*)d_in[4];

    float* y        = (float*)d_out;
    float* low_out  = y + (size_t)B_DIM * OUT_DIM;
    float* high_out = low_out + OUT_DIM;

    cudaFuncSetAttribute(abstract_linear_s8_kernel,
                         cudaFuncAttributeMaxDynamicSharedMemorySize, DSMEM_BYTES);

    quant_x_kernel<<<B_DIM, 256>>>(x);
    quant_w_kernel<<<OUT_DIM, 256>>>(W, low, high, bias, low_out, high_out);

    dim3 grid(B_DIM / BM, OUT_DIM / BN);  // (2, 64)
    abstract_linear_s8_kernel<<<grid, 256, DSMEM_BYTES>>>(bias, y);
}

// round 13
// speedup vs baseline: 1.2245x; 1.2245x over previous
#include <cuda_runtime.h>
#include <cuda_bf16.h>
#include <cstdint>

#define K_DIM   8192
#define B_DIM   256
#define OUT_DIM 8192
#define BM      128
#define BN      128
#define KC      32
#define NT      (K_DIM / KC)            // 256 stages
#define RSTRIDE 80                      // tensor smem row stride (32 bf16 + pad)
#define A_SPL   (128 * RSTRIDE)         // 10240
#define B_SPL   (64 * RSTRIDE)          // 5120 (tensor B tiles are 64 n-rows)
#define XF_OFF  30720                   // after Ahi|Alo|Bhi|Blo
#define WF_OFF  (XF_OFF + 16384)        // Xf = 128 rows x 128B
#define SSTAGE  (WF_OFF + 8192)         // + Wf 64 rows x 128B = 55296
#define NSTAGE  3
#define DSMEM_BYTES (NSTAGE * SSTAGE)   // 165888

typedef unsigned long long u64;

// ---------------- scratch: bf16 split of x ----------------
__device__ __nv_bfloat16 g_x_hi[(size_t)B_DIM * K_DIM];
__device__ __nv_bfloat16 g_x_lo[(size_t)B_DIM * K_DIM];

// ---------------- helpers ----------------
__device__ __forceinline__ uint32_t smem_u32(const void* p) {
    uint32_t a;
    asm("{ .reg .u64 t; cvta.to.shared.u64 t, %1; cvt.u32.u64 %0, t; }" : "=r"(a) : "l"(p));
    return a;
}
__device__ __forceinline__ uint32_t cvt2(float hiVal, float loVal) {
    uint32_t r;
    asm("cvt.rn.bf16x2.f32 %0, %1, %2;" : "=r"(r) : "f"(hiVal), "f"(loVal));
    return r;
}
__device__ __forceinline__ void ffma2(u64& d, u64 a, u64 b) {
    asm("fma.rn.f32x2 %0, %1, %2, %0;" : "+l"(d) : "l"(a), "l"(b));
}
__device__ __forceinline__ void unpack2(u64 v, float& lo, float& hi) {
    asm("mov.b64 {%0, %1}, %2;" : "=f"(lo), "=f"(hi) : "l"(v));
}

#define LDSM4(r0, r1, r2, r3, addr) \
    asm volatile("ldmatrix.sync.aligned.m8n8.x4.shared.b16 {%0,%1,%2,%3}, [%4];" \
                 : "=r"(r0), "=r"(r1), "=r"(r2), "=r"(r3) : "r"(addr))

#define MMA(c, a, b) \
    asm volatile("mma.sync.aligned.m16n8k16.row.col.f32.bf16.bf16.f32 " \
                 "{%0,%1,%2,%3}, {%4,%5,%6,%7}, {%8,%9}, {%0,%1,%2,%3};" \
                 : "+f"((c)[0]), "+f"((c)[1]), "+f"((c)[2]), "+f"((c)[3]) \
                 : "r"((a)[0]), "r"((a)[1]), "r"((a)[2]), "r"((a)[3]), \
                   "r"((b)[0]), "r"((b)[1]))

#define CP_ASYNC16(dst, src) \
    asm volatile("cp.async.cg.shared.global [%0], [%1], 16;" :: "r"(dst), "l"(src) : "memory")
#define CP_COMMIT() asm volatile("cp.async.commit_group;" ::: "memory")
#define CP_WAIT1()  asm volatile("cp.async.wait_group 1;" ::: "memory")
#define CP_WAIT0()  asm volatile("cp.async.wait_group 0;" ::: "memory")

// ---------------- kernel 1: split x into bf16 hi/lo ----------------
__global__ __launch_bounds__(256)
void convert_x_kernel(const float* __restrict__ x) {
    size_t i = ((size_t)blockIdx.x * 256 + threadIdx.x) * 8;
    float4 a = *reinterpret_cast<const float4*>(x + i);
    float4 b = *reinterpret_cast<const float4*>(x + i + 4);
    uint32_t h0 = cvt2(a.y, a.x), h1 = cvt2(a.w, a.z);
    uint32_t h2 = cvt2(b.y, b.x), h3 = cvt2(b.w, b.z);
    float l0 = a.x - __uint_as_float(h0 << 16);
    float l1 = a.y - __uint_as_float(h0 & 0xffff0000u);
    float l2 = a.z - __uint_as_float(h1 << 16);
    float l3 = a.w - __uint_as_float(h1 & 0xffff0000u);
    float l4 = b.x - __uint_as_float(h2 << 16);
    float l5 = b.y - __uint_as_float(h2 & 0xffff0000u);
    float l6 = b.z - __uint_as_float(h3 << 16);
    float l7 = b.w - __uint_as_float(h3 & 0xffff0000u);
    *reinterpret_cast<uint4*>(g_x_hi + i) = make_uint4(h0, h1, h2, h3);
    *reinterpret_cast<uint4*>(g_x_lo + i) =
        make_uint4(cvt2(l1, l0), cvt2(l3, l2), cvt2(l5, l4), cvt2(l7, l6));
}

// ---------------- kernel 2: dual-pipe GEMM (tensor n[0:64] + fp32 fma n[64:128]) ----------------
__global__ __launch_bounds__(512, 1)
void abstract_linear_dual_kernel(const float* __restrict__ x,
                                 const float* __restrict__ low,
                                 const float* __restrict__ high,
                                 const float* __restrict__ W,
                                 const float* __restrict__ bias,
                                 float* __restrict__ y,
                                 float* __restrict__ low_out,
                                 float* __restrict__ high_out)
{
    extern __shared__ __align__(128) char dsm[];
    const uint32_t sbase = smem_u32(dsm);

    const int tid  = threadIdx.x;
    const int lane = tid & 31;
    const int wid  = tid >> 5;            // 0..15
    const int nBase = blockIdx.x * BN;
    const int mBase = blockIdx.y * BM;
    const bool doB = (blockIdx.y == 0);

    if (wid < 8) {
        // ============ TENSOR PATH: 3-term bf16 split, n[0:64] ============
        const int wm = wid >> 2;   // 0..1  (64 m-rows)
        const int wn = wid & 3;    // 0..3  (16 n-cols)

        // x loader (cp.async): thread -> (split, row), 64B
        const int xrow = tid & 127;
        const bool isHi = (tid < 128);
        const __nv_bfloat16* xg = (isHi ? g_x_hi : g_x_lo) + (size_t)(mBase + xrow) * K_DIM;
        const uint32_t xdstBase = (isHi ? 0u : (uint32_t)A_SPL) + (uint32_t)xrow * RSTRIDE;

        // W loader: thread -> (row 0..127, 16-elem k half)
        const int wrow = tid >> 1;
        const int lkh  = tid & 1;
        const float* wg = W + (size_t)(nBase + wrow) * K_DIM + lkh * 16;
        const uint32_t wsts = (uint32_t)(wrow & 63) * RSTRIDE + lkh * 32;

        const uint32_t aOff = (uint32_t)(wm * 64 + (lane & 15)) * RSTRIDE + (lane >> 4) * 16;
        const uint32_t bOff = (uint32_t)(wn * 16 + (lane & 7) + ((lane >> 4) & 1) * 8) * RSTRIDE
                            + ((lane >> 3) & 1) * 16;

        float acc[4][2][4];
        #pragma unroll
        for (int i = 0; i < 4; ++i)
            #pragma unroll
            for (int j = 0; j < 2; ++j)
                #pragma unroll
                for (int r = 0; r < 4; ++r) acc[i][j][r] = 0.f;

        float boundLo = 0.f, boundHi = 0.f;
        float4 wv[4];

        auto cpX = [&](int stage, int kt) {
            const uint32_t dst = sbase + stage * SSTAGE + xdstBase;
            const __nv_bfloat16* src = xg + kt * KC;
            CP_ASYNC16(dst,      src);      CP_ASYNC16(dst + 16, src + 8);
            CP_ASYNC16(dst + 32, src + 16); CP_ASYNC16(dst + 48, src + 24);
            CP_COMMIT();
        };

        auto loadW = [&](int kt) {
            #pragma unroll
            for (int i = 0; i < 4; ++i)
                wv[i] = *reinterpret_cast<const float4*>(wg + (size_t)kt * KC + i * 4);
        };

        auto stashW = [&](int stage, int kt) {
            if (wrow < 64) {
                // convert -> bf16 split tiles for tensor path
                char* bHp = dsm + (size_t)stage * SSTAGE + 2 * A_SPL + wsts;
                char* bLp = bHp + B_SPL;
                #pragma unroll
                for (int i = 0; i < 2; ++i) {
                    const float4 a = wv[2 * i], b = wv[2 * i + 1];
                    uint32_t h0 = cvt2(a.y, a.x), h1 = cvt2(a.w, a.z);
                    uint32_t h2 = cvt2(b.y, b.x), h3 = cvt2(b.w, b.z);
                    float l0 = a.x - __uint_as_float(h0 << 16);
                    float l1 = a.y - __uint_as_float(h0 & 0xffff0000u);
                    float l2 = a.z - __uint_as_float(h1 << 16);
                    float l3 = a.w - __uint_as_float(h1 & 0xffff0000u);
                    float l4 = b.x - __uint_as_float(h2 << 16);
                    float l5 = b.y - __uint_as_float(h2 & 0xffff0000u);
                    float l6 = b.z - __uint_as_float(h3 << 16);
                    float l7 = b.w - __uint_as_float(h3 & 0xffff0000u);
                    *reinterpret_cast<uint4*>(bHp + i * 16) = make_uint4(h0, h1, h2, h3);
                    *reinterpret_cast<uint4*>(bLp + i * 16) =
                        make_uint4(cvt2(l1, l0), cvt2(l3, l2), cvt2(l5, l4), cvt2(l7, l6));
                }
            } else {
                // fp32 -> Wf tile for fma path (XOR-swizzled 16B chunks)
                const int nf = wrow - 64;
                char* wfp = dsm + (size_t)stage * SSTAGE + WF_OFF + (size_t)nf * 128;
                const int sw = (nf >> 2) & 7;
                #pragma unroll
                for (int j = 0; j < 4; ++j)
                    *reinterpret_cast<float4*>(wfp + (((lkh * 4 + j) ^ sw) * 16)) = wv[j];
            }
            if (doB) {
                #pragma unroll
                for (int j = 0; j < 4; ++j) {
                    const float4 a = wv[j];
                    const float* lp = low  + kt * KC + lkh * 16 + j * 4;
                    const float* hp = high + kt * KC + lkh * 16 + j * 4;
                    const float4 la = *reinterpret_cast<const float4*>(lp);
                    const float4 ha = *reinterpret_cast<const float4*>(hp);
                    float p, q;
                    p = a.x * la.x; q = a.x * ha.x; boundLo += fminf(p, q); boundHi += fmaxf(p, q);
                    p = a.y * la.y; q = a.y * ha.y; boundLo += fminf(p, q); boundHi += fmaxf(p, q);
                    p = a.z * la.z; q = a.z * ha.z; boundLo += fminf(p, q); boundHi += fmaxf(p, q);
                    p = a.w * la.w; q = a.w * ha.w; boundLo += fminf(p, q); boundHi += fmaxf(p, q);
                }
            }
        };

        auto doMMA = [&](int stage) {
            const uint32_t base = sbase + stage * SSTAGE;
            const uint32_t A_hi = base, A_lo = base + A_SPL;
            const uint32_t B_hi = base + 2 * A_SPL, B_lo = B_hi + B_SPL;
            #pragma unroll
            for (int k16 = 0; k16 < 2; ++k16) {
                uint32_t aH[4][4], aL[4][4], bH[2][2], bL[2][2];
                #pragma unroll
                for (int mf = 0; mf < 4; ++mf) {
                    LDSM4(aH[mf][0], aH[mf][1], aH[mf][2], aH[mf][3],
                          A_hi + aOff + mf * (16 * RSTRIDE) + k16 * 32);
                    LDSM4(aL[mf][0], aL[mf][1], aL[mf][2], aL[mf][3],
                          A_lo + aOff + mf * (16 * RSTRIDE) + k16 * 32);
                }
                uint32_t q0, q1, q2, q3;
                LDSM4(q0, q1, q2, q3, B_hi + bOff + k16 * 32);
                bH[0][0] = q0; bH[0][1] = q1; bH[1][0] = q2; bH[1][1] = q3;
                LDSM4(q0, q1, q2, q3, B_lo + bOff + k16 * 32);
                bL[0][0] = q0; bL[0][1] = q1; bL[1][0] = q2; bL[1][1] = q3;
                #pragma unroll
                for (int mf = 0; mf < 4; ++mf)
                    #pragma unroll
                    for (int nf = 0; nf < 2; ++nf) MMA(acc[mf][nf], aH[mf], bH[nf]);
                #pragma unroll
                for (int mf = 0; mf < 4; ++mf)
                    #pragma unroll
                    for (int nf = 0; nf < 2; ++nf) MMA(acc[mf][nf], aH[mf], bL[nf]);
                #pragma unroll
                for (int mf = 0; mf < 4; ++mf)
                    #pragma unroll
                    for (int nf = 0; nf < 2; ++nf) MMA(acc[mf][nf], aL[mf], bH[nf]);
            }
        };

        // prologue
        cpX(0, 0); cpX(1, 1);
        loadW(0);
        stashW(0, 0);
        CP_WAIT1();
        __syncthreads();

        #pragma unroll 1
        for (int kt = 0; kt < NT; ++kt) {
            const int stage = kt % NSTAGE;
            if (kt + 2 < NT) cpX((kt + 2) % NSTAGE, kt + 2);
            if (kt + 1 < NT) loadW(kt + 1);
            doMMA(stage);
            if (kt + 1 < NT) stashW((kt + 1) % NSTAGE, kt + 1);
            if (kt + 2 < NT) { CP_WAIT1(); } else { CP_WAIT0(); }
            __syncthreads();
        }

        // epilogue: y (tensor half)
        #pragma unroll
        for (int mf = 0; mf < 4; ++mf) {
            const int r0 = mBase + wm * 64 + mf * 16 + (lane >> 2);
            #pragma unroll
            for (int nf = 0; nf < 2; ++nf) {
                const int c = nBase + wn * 16 + nf * 8 + (lane & 3) * 2;
                const float2 bv = *reinterpret_cast<const float2*>(bias + c);
                float2 o0 = make_float2(acc[mf][nf][0] + bv.x, acc[mf][nf][1] + bv.y);
                float2 o1 = make_float2(acc[mf][nf][2] + bv.x, acc[mf][nf][3] + bv.y);
                *reinterpret_cast<float2*>(y + (size_t)r0 * OUT_DIM + c) = o0;
                *reinterpret_cast<float2*>(y + (size_t)(r0 + 8) * OUT_DIM + c) = o1;
            }
        }

        // epilogue: bounds (all 128 n-rows, width-2 reduction)
        if (doB) {
            boundLo += __shfl_xor_sync(0xffffffffu, boundLo, 1);
            boundHi += __shfl_xor_sync(0xffffffffu, boundHi, 1);
            if (lkh == 0) {
                const int r = nBase + wrow;
                const float bb = bias[r];
                low_out[r]  = boundLo + bb;
                high_out[r] = boundHi + bb;
            }
        }
    } else {
        // ============ FMA PATH: exact fp32 f32x2 dot-products, n[64:128] ============
        const int ftid = tid - 256;          // 0..255
        const int fy = ftid >> 4;            // 0..15  (8 m-rows each)
        const int fx = ftid & 15;            // 0..15  (4 n-cols each)

        // Xf loader: thread -> (row, half), 64B each
        const int xr = ftid >> 1;            // 0..127
        const int xh = ftid & 1;
        const float* xgf = x + (size_t)(mBase + xr) * K_DIM + xh * 16;
        const uint32_t xfdst = (uint32_t)xr * 128 + xh * 64;

        u64 acc2[8][4];
        #pragma unroll
        for (int i = 0; i < 8; ++i)
            #pragma unroll
            for (int j = 0; j < 4; ++j) acc2[i][j] = 0ull;

        auto cpXf = [&](int stage, int kt) {
            const uint32_t dst = sbase + stage * SSTAGE + XF_OFF + xfdst;
            const float* src = xgf + (size_t)kt * KC;
            CP_ASYNC16(dst,      src);      CP_ASYNC16(dst + 16, src + 4);
            CP_ASYNC16(dst + 32, src + 8);  CP_ASYNC16(dst + 48, src + 12);
            CP_COMMIT();
        };

        auto doFMA = [&](int stage) {
            const char* xfb = dsm + (size_t)stage * SSTAGE + XF_OFF + (size_t)(fy * 8) * 128;
            const char* wfb = dsm + (size_t)stage * SSTAGE + WF_OFF + (size_t)(fx * 4) * 128;
            const int sw = fx & 7;
            #pragma unroll
            for (int k4 = 0; k4 < 8; ++k4) {
                ulonglong2 a4[8], b4[4];
                #pragma unroll
                for (int mr = 0; mr < 8; ++mr)
                    a4[mr] = *reinterpret_cast<const ulonglong2*>(xfb + mr * 128 + k4 * 16);
                const int bc = (k4 ^ sw) * 16;
                #pragma unroll
                for (int nr = 0; nr < 4; ++nr)
                    b4[nr] = *reinterpret_cast<const ulonglong2*>(wfb + nr * 128 + bc);
                #pragma unroll
                for (int mr = 0; mr < 8; ++mr)
                    #pragma unroll
                    for (int nr = 0; nr < 4; ++nr) ffma2(acc2[mr][nr], a4[mr].x, b4[nr].x);
                #pragma unroll
                for (int mr = 0; mr < 8; ++mr)
                    #pragma unroll
                    for (int nr = 0; nr < 4; ++nr) ffma2(acc2[mr][nr], a4[mr].y, b4[nr].y);
            }
        };

        // prologue
        cpXf(0, 0); cpXf(1, 1);
        CP_WAIT1();
        __syncthreads();

        #pragma unroll 1
        for (int kt = 0; kt < NT; ++kt) {
            const int stage = kt % NSTAGE;
            if (kt + 2 < NT) cpXf((kt + 2) % NSTAGE, kt + 2);
            doFMA(stage);
            if (kt + 2 < NT) { CP_WAIT1(); } else { CP_WAIT0(); }
            __syncthreads();
        }

        // epilogue: y (fma half) — exact fp32
        const int col = nBase + 64 + fx * 4;
        const float4 bv = *reinterpret_cast<const float4*>(bias + col);
        #pragma unroll
        for (int mr = 0; mr < 8; ++mr) {
            const int row = mBase + fy * 8 + mr;
            float s0a, s0b, s1a, s1b, s2a, s2b, s3a, s3b;
            unpack2(acc2[mr][0], s0a, s0b);
            unpack2(acc2[mr][1], s1a, s1b);
            unpack2(acc2[mr][2], s2a, s2b);
            unpack2(acc2[mr][3], s3a, s3b);
            float4 o = make_float4(s0a + s0b + bv.x, s1a + s1b + bv.y,
                                   s2a + s2b + bv.z, s3a + s3b + bv.w);
            *reinterpret_cast<float4*>(y + (size_t)row * OUT_DIM + col) = o;
        }
    }
}

extern "C" void kernel_launch(void* const* d_in, const int* in_sizes, int n_in,
                              void* d_out, int out_size) {
    const float* x    = (const float*)d_in[0];
    const float* low  = (const float*)d_in[1];
    const float* high = (const float*)d_in[2];
    const float* W    = (const float*)d_in[3];
    const float* bias = (const float*)d_in[4];

    float* y        = (float*)d_out;
    float* low_out  = y + (size_t)B_DIM * OUT_DIM;
    float* high_out = low_out + OUT_DIM;

    cudaFuncSetAttribute(abstract_linear_dual_kernel,
                         cudaFuncAttributeMaxDynamicSharedMemorySize, DSMEM_BYTES);

    convert_x_kernel<<<(B_DIM * K_DIM) / (256 * 8), 256>>>(x);

    dim3 grid(OUT_DIM / BN, B_DIM / BM);  // (64, 2) = 128 CTAs
    abstract_linear_dual_kernel<<<grid, 512, DSMEM_BYTES>>>(x, low, high, W, bias,
                                                            y, low_out, high_out);
}

// round 14
// speedup vs baseline: 2.0780x; 1.6971x over previous
#include <cuda_runtime.h>
#include <cuda_bf16.h>
#include <cstdint>

#define K_DIM   8192
#define B_DIM   256
#define OUT_DIM 8192
#define BM      128
#define BN      128
#define KC      32
#define NT      (K_DIM / KC)          // 256 stages
#define RSTRIDE 80                    // bytes per smem row (32 bf16 + 16B pad)
#define SPLIT_BYTES (128 * RSTRIDE)   // 10240 per split tile
#define STAGE_BYTES (4 * SPLIT_BYTES) // A_hi|A_lo|B_hi|B_lo = 40960
#define NSTAGE  3
#define LH_OFF  (NSTAGE * STAGE_BYTES)        // 122880: low[8192] | high[8192]
#define DSMEM_BYTES (LH_OFF + 2 * K_DIM * 4)  // 188416

// ---------------- scratch: bf16 split of x ----------------
__device__ __nv_bfloat16 g_x_hi[(size_t)B_DIM * K_DIM];
__device__ __nv_bfloat16 g_x_lo[(size_t)B_DIM * K_DIM];

// ---------------- helpers ----------------
__device__ __forceinline__ uint32_t smem_u32(const void* p) {
    uint32_t a;
    asm("{ .reg .u64 t; cvta.to.shared.u64 t, %1; cvt.u32.u64 %0, t; }" : "=r"(a) : "l"(p));
    return a;
}
__device__ __forceinline__ uint32_t cvt2(float hiVal, float loVal) {
    uint32_t r;
    asm("cvt.rn.bf16x2.f32 %0, %1, %2;" : "=r"(r) : "f"(hiVal), "f"(loVal));
    return r;
}

#define LDSM4(r0, r1, r2, r3, addr) \
    asm volatile("ldmatrix.sync.aligned.m8n8.x4.shared.b16 {%0,%1,%2,%3}, [%4];" \
                 : "=r"(r0), "=r"(r1), "=r"(r2), "=r"(r3) : "r"(addr))

#define MMA(c, a, b) \
    asm volatile("mma.sync.aligned.m16n8k16.row.col.f32.bf16.bf16.f32 " \
                 "{%0,%1,%2,%3}, {%4,%5,%6,%7}, {%8,%9}, {%0,%1,%2,%3};" \
                 : "+f"((c)[0]), "+f"((c)[1]), "+f"((c)[2]), "+f"((c)[3]) \
                 : "r"((a)[0]), "r"((a)[1]), "r"((a)[2]), "r"((a)[3]), \
                   "r"((b)[0]), "r"((b)[1]))

#define CP_ASYNC16(dst, src) \
    asm volatile("cp.async.cg.shared.global [%0], [%1], 16;" :: "r"(dst), "l"(src) : "memory")
#define CP_COMMIT() asm volatile("cp.async.commit_group;" ::: "memory")
#define CP_WAIT1()  asm volatile("cp.async.wait_group 1;" ::: "memory")
#define CP_WAIT0()  asm volatile("cp.async.wait_group 0;" ::: "memory")

// ---------------- kernel 1: split x into bf16 hi/lo ----------------
__global__ __launch_bounds__(256)
void convert_x_kernel(const float* __restrict__ x) {
    size_t i = ((size_t)blockIdx.x * 256 + threadIdx.x) * 8;
    float4 a = *reinterpret_cast<const float4*>(x + i);
    float4 b = *reinterpret_cast<const float4*>(x + i + 4);
    uint32_t h0 = cvt2(a.y, a.x), h1 = cvt2(a.w, a.z);
    uint32_t h2 = cvt2(b.y, b.x), h3 = cvt2(b.w, b.z);
    float l0 = a.x - __uint_as_float(h0 << 16);
    float l1 = a.y - __uint_as_float(h0 & 0xffff0000u);
    float l2 = a.z - __uint_as_float(h1 << 16);
    float l3 = a.w - __uint_as_float(h1 & 0xffff0000u);
    float l4 = b.x - __uint_as_float(h2 << 16);
    float l5 = b.y - __uint_as_float(h2 & 0xffff0000u);
    float l6 = b.z - __uint_as_float(h3 << 16);
    float l7 = b.w - __uint_as_float(h3 & 0xffff0000u);
    *reinterpret_cast<uint4*>(g_x_hi + i) = make_uint4(h0, h1, h2, h3);
    *reinterpret_cast<uint4*>(g_x_lo + i) =
        make_uint4(cvt2(l1, l0), cvt2(l3, l2), cvt2(l5, l4), cvt2(l7, l6));
}

// ---------------- kernel 2: split-bf16 mma GEMM + fused IBP ----------------
__global__ __launch_bounds__(256, 1)
void abstract_linear_mma_kernel(const float* __restrict__ low,
                                const float* __restrict__ high,
                                const float* __restrict__ W,
                                const float* __restrict__ bias,
                                float* __restrict__ y,
                                float* __restrict__ low_out,
                                float* __restrict__ high_out)
{
    extern __shared__ __align__(128) char dsm[];
    const uint32_t sbase = smem_u32(dsm);

    const int tid  = threadIdx.x;
    const int lane = tid & 31;
    const int wid  = tid >> 5;       // 0..7
    const int nBase = blockIdx.x * BN;
    const int mBase = blockIdx.y * BM;
    const bool doB = (blockIdx.y == 0);

    const int wm = wid >> 2;   // 0..1  (m direction, 64 rows each)
    const int wn = wid & 3;    // 0..3  (n direction, 32 cols each)

    // ---- preload low/high into smem (doB CTAs only use it; load unconditionally) ----
    float* s_low  = reinterpret_cast<float*>(dsm + LH_OFF);
    float* s_high = s_low + K_DIM;
    if (doB) {
        #pragma unroll
        for (int i = 0; i < 8; ++i) {
            const int idx = (tid + i * 256) * 4;
            *reinterpret_cast<float4*>(s_low + idx)  = *reinterpret_cast<const float4*>(low + idx);
            *reinterpret_cast<float4*>(s_high + idx) = *reinterpret_cast<const float4*>(high + idx);
        }
    }

    // ---- x loader (cp.async): thread -> (split, row): 64B per thread ----
    const int xrow = tid & 127;
    const bool isHi = (tid < 128);
    const __nv_bfloat16* xg = (isHi ? g_x_hi : g_x_lo) + (size_t)(mBase + xrow) * K_DIM;
    const uint32_t xdstBase = (isHi ? 0u : (uint32_t)SPLIT_BYTES) + (uint32_t)xrow * RSTRIDE;

    // ---- W loader: thread -> (row, 16-elem k half) ----
    const int wrow = tid >> 1;        // 0..127
    const int lkh  = tid & 1;         // k half (16 elems)
    const float* wg = W + (size_t)(nBase + wrow) * K_DIM + lkh * 16;
    const uint32_t wsts = (uint32_t)wrow * RSTRIDE + lkh * 32;

    // ---- ldmatrix per-thread offsets ----
    const uint32_t aOff = (uint32_t)(wm * 64 + (lane & 15)) * RSTRIDE + (lane >> 4) * 16;
    const uint32_t bOff = (uint32_t)(wn * 32 + (lane & 7) + ((lane >> 4) & 1) * 8) * RSTRIDE
                        + ((lane >> 3) & 1) * 16;

    float acc[4][4][4];
    #pragma unroll
    for (int i = 0; i < 4; ++i)
        #pragma unroll
        for (int j = 0; j < 4; ++j)
            #pragma unroll
            for (int r = 0; r < 4; ++r) acc[i][j][r] = 0.f;

    float boundLo = 0.f, boundHi = 0.f;
    float4 wv[4];   // 16 floats: this thread's full k-half of one W row

    auto cpX = [&](int stage, int kt) {
        const uint32_t dst = sbase + stage * STAGE_BYTES + xdstBase;
        const __nv_bfloat16* src = xg + kt * KC;
        CP_ASYNC16(dst,      src);
        CP_ASYNC16(dst + 16, src + 8);
        CP_ASYNC16(dst + 32, src + 16);
        CP_ASYNC16(dst + 48, src + 24);
        CP_COMMIT();
    };

    auto loadW = [&](int kt) {
        #pragma unroll
        for (int i = 0; i < 4; ++i)
            wv[i] = *reinterpret_cast<const float4*>(wg + (size_t)kt * KC + i * 4);
    };

    auto stashW = [&](int stage, int kt) {
        char* bHp = dsm + (size_t)stage * STAGE_BYTES + 2 * SPLIT_BYTES + wsts;
        char* bLp = bHp + SPLIT_BYTES;
        #pragma unroll
        for (int i = 0; i < 2; ++i) {
            const float4 a = wv[2 * i], b = wv[2 * i + 1];
            uint32_t h0 = cvt2(a.y, a.x), h1 = cvt2(a.w, a.z);
            uint32_t h2 = cvt2(b.y, b.x), h3 = cvt2(b.w, b.z);
            float l0 = a.x - __uint_as_float(h0 << 16);
            float l1 = a.y - __uint_as_float(h0 & 0xffff0000u);
            float l2 = a.z - __uint_as_float(h1 << 16);
            float l3 = a.w - __uint_as_float(h1 & 0xffff0000u);
            float l4 = b.x - __uint_as_float(h2 << 16);
            float l5 = b.y - __uint_as_float(h2 & 0xffff0000u);
            float l6 = b.z - __uint_as_float(h3 << 16);
            float l7 = b.w - __uint_as_float(h3 & 0xffff0000u);
            *reinterpret_cast<uint4*>(bHp + i * 16) = make_uint4(h0, h1, h2, h3);
            *reinterpret_cast<uint4*>(bLp + i * 16) =
                make_uint4(cvt2(l1, l0), cvt2(l3, l2), cvt2(l5, l4), cvt2(l7, l6));
            if (doB) {
                const float* lp = s_low  + kt * KC + lkh * 16 + i * 8;
                const float* hp = s_high + kt * KC + lkh * 16 + i * 8;
                const float4 la = *reinterpret_cast<const float4*>(lp);
                const float4 lb = *reinterpret_cast<const float4*>(lp + 4);
                const float4 ha = *reinterpret_cast<const float4*>(hp);
                const float4 hb = *reinterpret_cast<const float4*>(hp + 4);
                float p, q;
                p = a.x * la.x; q = a.x * ha.x; boundLo += fminf(p, q); boundHi += fmaxf(p, q);
                p = a.y * la.y; q = a.y * ha.y; boundLo += fminf(p, q); boundHi += fmaxf(p, q);
                p = a.z * la.z; q = a.z * ha.z; boundLo += fminf(p, q); boundHi += fmaxf(p, q);
                p = a.w * la.w; q = a.w * ha.w; boundLo += fminf(p, q); boundHi += fmaxf(p, q);
                p = b.x * lb.x; q = b.x * hb.x; boundLo += fminf(p, q); boundHi += fmaxf(p, q);
                p = b.y * lb.y; q = b.y * hb.y; boundLo += fminf(p, q); boundHi += fmaxf(p, q);
                p = b.z * lb.z; q = b.z * hb.z; boundLo += fminf(p, q); boundHi += fmaxf(p, q);
                p = b.w * lb.w; q = b.w * hb.w; boundLo += fminf(p, q); boundHi += fmaxf(p, q);
            }
        }
    };

    auto doMMA = [&](int stage) {
        const uint32_t A_hi = sbase + stage * STAGE_BYTES;
        const uint32_t A_lo = A_hi + SPLIT_BYTES;
        const uint32_t B_hi = A_hi + 2 * SPLIT_BYTES;
        const uint32_t B_lo = A_hi + 3 * SPLIT_BYTES;
        #pragma unroll
        for (int k16 = 0; k16 < 2; ++k16) {
            uint32_t aH[4][4], aL[4][4], bH[4][2], bL[4][2];
            #pragma unroll
            for (int mf = 0; mf < 4; ++mf) {
                LDSM4(aH[mf][0], aH[mf][1], aH[mf][2], aH[mf][3],
                      A_hi + aOff + mf * (16 * RSTRIDE) + k16 * 32);
                LDSM4(aL[mf][0], aL[mf][1], aL[mf][2], aL[mf][3],
                      A_lo + aOff + mf * (16 * RSTRIDE) + k16 * 32);
            }
            #pragma unroll
            for (int p = 0; p < 2; ++p) {
                uint32_t r0, r1, r2, r3;
                LDSM4(r0, r1, r2, r3, B_hi + bOff + p * (16 * RSTRIDE) + k16 * 32);
                bH[2 * p][0] = r0; bH[2 * p][1] = r1;
                bH[2 * p + 1][0] = r2; bH[2 * p + 1][1] = r3;
                LDSM4(r0, r1, r2, r3, B_lo + bOff + p * (16 * RSTRIDE) + k16 * 32);
                bL[2 * p][0] = r0; bL[2 * p][1] = r1;
                bL[2 * p + 1][0] = r2; bL[2 * p + 1][1] = r3;
            }
            // term-major: 16 independent MMAs between accumulator reuses
            #pragma unroll
            for (int mf = 0; mf < 4; ++mf)
                #pragma unroll
                for (int nf = 0; nf < 4; ++nf) MMA(acc[mf][nf], aH[mf], bH[nf]);
            #pragma unroll
            for (int mf = 0; mf < 4; ++mf)
                #pragma unroll
                for (int nf = 0; nf < 4; ++nf) MMA(acc[mf][nf], aH[mf], bL[nf]);
            #pragma unroll
            for (int mf = 0; mf < 4; ++mf)
                #pragma unroll
                for (int nf = 0; nf < 4; ++nf) MMA(acc[mf][nf], aL[mf], bH[nf]);
        }
    };

    // ---- prologue: x stages 0,1 in flight; W stage 0 stashed; W stage 1 in regs ----
    cpX(0, 0);
    cpX(1, 1);
    loadW(0);
    stashW(0, 0);       // note: uses gmem low/high timing-wise irrelevant? uses s_low BEFORE sync
    // s_low/s_high are written by this same thread set above without a sync yet;
    // stashW(0) for doB reads s_low — need the preload visible: barrier first.
    // (Correctness fix: sync between preload and first stash for doB CTAs.)
    loadW(1);
    CP_WAIT1();
    __syncthreads();

    // ---- main loop: stash(kt+1) -> cp/load(kt+2) -> MMA(kt) ----
    #pragma unroll 1
    for (int kt = 0; kt < NT; ++kt) {
        const int stage = kt % NSTAGE;
        if (kt + 1 < NT) stashW((kt + 1) % NSTAGE, kt + 1);   // W regs from prev iter
        if (kt + 2 < NT) {
            cpX((kt + 2) % NSTAGE, kt + 2);
            loadW(kt + 2);                                     // full stage to land
        }
        doMMA(stage);
        if (kt + 2 < NT) { CP_WAIT1(); } else { CP_WAIT0(); }
        __syncthreads();
    }

    // ---- epilogue: y = acc + bias ----
    #pragma unroll
    for (int mf = 0; mf < 4; ++mf) {
        const int r0 = mBase + wm * 64 + mf * 16 + (lane >> 2);
        #pragma unroll
        for (int nf = 0; nf < 4; ++nf) {
            const int c = nBase + wn * 32 + nf * 8 + (lane & 3) * 2;
            const float2 bv = *reinterpret_cast<const float2*>(bias + c);
            float2 o0 = make_float2(acc[mf][nf][0] + bv.x, acc[mf][nf][1] + bv.y);
            float2 o1 = make_float2(acc[mf][nf][2] + bv.x, acc[mf][nf][3] + bv.y);
            *reinterpret_cast<float2*>(y + (size_t)r0 * OUT_DIM + c) = o0;
            *reinterpret_cast<float2*>(y + (size_t)(r0 + 8) * OUT_DIM + c) = o1;
        }
    }

    // ---- epilogue: bounds (width-2 deterministic reduction) ----
    if (doB) {
        boundLo += __shfl_xor_sync(0xffffffffu, boundLo, 1);
        boundHi += __shfl_xor_sync(0xffffffffu, boundHi, 1);
        if (lkh == 0) {
            const int r = nBase + wrow;
            const float bb = bias[r];
            low_out[r]  = boundLo + bb;
            high_out[r] = boundHi + bb;
        }
    }
}

extern "C" void kernel_launch(void* const* d_in, const int* in_sizes, int n_in,
                              void* d_out, int out_size) {
    const float* x    = (const float*)d_in[0];
    const float* low  = (const float*)d_in[1];
    const float* high = (const float*)d_in[2];
    const float* W    = (const float*)d_in[3];
    const float* bias = (const float*)d_in[4];

    float* y        = (float*)d_out;
    float* low_out  = y + (size_t)B_DIM * OUT_DIM;
    float* high_out = low_out + OUT_DIM;

    cudaFuncSetAttribute(abstract_linear_mma_kernel,
                         cudaFuncAttributeMaxDynamicSharedMemorySize, DSMEM_BYTES);

    convert_x_kernel<<<(B_DIM * K_DIM) / (256 * 8), 256>>>(x);

    dim3 grid(OUT_DIM / BN, B_DIM / BM);  // (64, 2) = 128 CTAs
    abstract_linear_mma_kernel<<<grid, 256, DSMEM_BYTES>>>(low, high, W, bias,
                                                           y, low_out, high_out);
}